// round 11
// baseline (speedup 1.0000x reference)
#include <cuda_runtime.h>
#include <math.h>
#include <cstdint>

// ---------------------------------------------------------------------------
// PreQ round 11: R8 pipeline with 3-CTA/SM GEMMs.
//   L1: x fp32 -> h1 [M,200], NWT=4 (NTC=64), NSPLIT=4, 3-stage ring, occ 3.
//   L2: h1 -> h2 [M,100], NWT=4, NSPLIT=2, occ 3.
//   L3: h2 -> fused layer4 + quantum fidelity, NWT=4, occ 2 (R8-style).
// tf32 mma.sync m16n8k8 (rel_err 1.28e-4, validated R6-R10).
// ---------------------------------------------------------------------------

#define MROWS 131072   // 2 * 65536

__device__ float g_h1[(size_t)MROWS * 200];
__device__ float g_h2[(size_t)MROWS * 100];
__device__ __align__(16) unsigned char g_w1f[256 * 1280];
__device__ __align__(16) unsigned char g_w2f[128 * 896];
__device__ __align__(16) unsigned char g_w3f[64 * 512];

// ---------------- helpers ----------------
__device__ __forceinline__ uint32_t smem_u32(const void* p) {
    uint32_t a;
    asm("{ .reg .u64 t; cvta.to.shared.u64 t, %1; cvt.u32.u64 %0, t; }"
        : "=r"(a) : "l"(p));
    return a;
}
__device__ __forceinline__ void cpa16(uint32_t dst, const void* src) {
    asm volatile("cp.async.cg.shared.global [%0], [%1], 16;"
                 :: "r"(dst), "l"(src) : "memory");
}
__device__ __forceinline__ void cpa16z(uint32_t dst, const void* src, int sz) {
    asm volatile("cp.async.cg.shared.global [%0], [%1], 16, %2;"
                 :: "r"(dst), "l"(src), "r"(sz) : "memory");
}
#define CP_COMMIT() asm volatile("cp.async.commit_group;" ::: "memory")
#define CP_WAIT0()  asm volatile("cp.async.wait_group 0;" ::: "memory")
#define CP_WAIT1()  asm volatile("cp.async.wait_group 1;" ::: "memory")

__device__ __forceinline__ uint32_t to_tf32(float f) {
    uint32_t r;
    asm("cvt.rna.tf32.f32 %0, %1;" : "=r"(r) : "f"(f));
    return r;
}
__device__ __forceinline__ void mma_tf32(float c[4],
                                         uint32_t a0, uint32_t a1,
                                         uint32_t a2, uint32_t a3,
                                         uint32_t b0, uint32_t b1) {
    asm volatile(
        "mma.sync.aligned.m16n8k8.row.col.f32.tf32.tf32.f32 "
        "{%0,%1,%2,%3}, {%4,%5,%6,%7}, {%8,%9}, {%0,%1,%2,%3};"
        : "+f"(c[0]), "+f"(c[1]), "+f"(c[2]), "+f"(c[3])
        : "r"(a0), "r"(a1), "r"(a2), "r"(a3), "r"(b0), "r"(b1));
}

// ---------------------------------------------------------------------------
// prep: W[src_rows, K] fp32 -> frag image [nrows_pad][nblk*64B], RN tf32.
// ---------------------------------------------------------------------------
__global__ void prep_frag(const float* __restrict__ S,
                          unsigned char* __restrict__ D,
                          int nrows_pad, int src_rows, int K, int nblk) {
    int f = blockIdx.x * blockDim.x + threadIdx.x;
    if (f >= nrows_pad * nblk) return;
    int row = f / nblk, eb = f - row * nblk;
    int k0 = eb * 16;
    float v[16];
    #pragma unroll
    for (int i = 0; i < 16; i++) v[i] = 0.f;
    if (row < src_rows) {
        #pragma unroll
        for (int i = 0; i < 4; i++) {
            int k = k0 + i * 4;
            if (k < K) {
                float4 q = *(const float4*)(S + (size_t)row * K + k);
                v[i * 4 + 0] = q.x; v[i * 4 + 1] = q.y;
                v[i * 4 + 2] = q.z; v[i * 4 + 3] = q.w;
            }
        }
    }
    uint32_t u[16];
    #pragma unroll
    for (int i = 0; i < 16; i++) u[i] = to_tf32(v[i]);
    unsigned char* dst = D + (size_t)row * (nblk * 64) + (size_t)eb * 64;
    #pragma unroll
    for (int tp = 0; tp < 4; tp++)
        *(uint4*)(dst + tp * 16) =
            make_uint4(u[tp], u[tp + 4], u[tp + 8], u[tp + 12]);
}

// ---------------- quantum math (verified rounds 1-10) ----------------
__device__ __forceinline__ float2 cadd(float2 a, float2 b) {
    return make_float2(a.x + b.x, a.y + b.y);
}
__device__ __forceinline__ float2 csc(float s, float2 a) {
    return make_float2(s * a.x, s * a.y);
}
__device__ __forceinline__ float2 cni(float s, float2 a) {
    return make_float2(s * a.y, -s * a.x);
}
__device__ void applyU(const float* __restrict__ p, float2 x[4]) {
    float c4, s4;
    __sincosf(0.5f * p[4], &s4, &c4);
    float2 y1 = make_float2(c4 * x[1].x + s4 * x[3].y,
                            c4 * x[1].y - s4 * x[3].x);
    float2 y3 = make_float2(s4 * x[1].y + c4 * x[3].x,
                           -s4 * x[1].x + c4 * x[3].y);
    x[1] = y1; x[3] = y3;
    float c2, s2, c3, s3;
    __sincosf(0.5f * p[2], &s2, &c2);
    __sincosf(0.5f * p[3], &s3, &c3);
    float2 t00 = cadd(csc(c3, x[0]), csc(-s3, x[1]));
    float2 t01 = cadd(csc(s3, x[0]), csc( c3, x[1]));
    float2 t10 = cadd(csc(c3, x[2]), csc(-s3, x[3]));
    float2 t11 = cadd(csc(s3, x[2]), csc( c3, x[3]));
    x[0] = cadd(csc(c2, t00), csc(-s2, t10));
    x[1] = cadd(csc(c2, t01), csc(-s2, t11));
    x[2] = cadd(csc(s2, t00), csc( c2, t10));
    x[3] = cadd(csc(s2, t01), csc( c2, t11));
    float c1, s1;
    __sincosf(0.5f * p[1], &s1, &c1);
    float2 u00 = cadd(csc(c1, x[0]), cni(s1, x[1]));
    float2 u01 = cadd(cni(s1, x[0]), csc(c1, x[1]));
    float2 u10 = cadd(csc(c1, x[2]), cni(s1, x[3]));
    float2 u11 = cadd(cni(s1, x[2]), csc(c1, x[3]));
    x[0] = cadd(csc(c1, u00), cni(s1, u10));
    x[1] = cadd(csc(c1, u01), cni(s1, u11));
    x[2] = cadd(cni(s1, u00), csc(c1, u10));
    x[3] = cadd(cni(s1, u01), csc(c1, u11));
}
__device__ __forceinline__ float fidelity_from(const float* l1, const float* l2) {
    float2 s1[4] = {make_float2(1.f, 0.f), make_float2(0.f, 0.f),
                    make_float2(0.f, 0.f), make_float2(0.f, 0.f)};
    applyU(l1, s1);
    applyU(l1 + 5, s1);
    float2 s2[4] = {make_float2(1.f, 0.f), make_float2(0.f, 0.f),
                    make_float2(0.f, 0.f), make_float2(0.f, 0.f)};
    applyU(l2, s2);
    applyU(l2 + 5, s2);
    float re = 0.f, im = 0.f;
    #pragma unroll
    for (int i = 0; i < 4; i++) {
        re += s2[i].x * s1[i].x + s2[i].y * s1[i].y;
        im += s2[i].x * s1[i].y - s2[i].y * s1[i].x;
    }
    return re * re + im * im;
}

// ---------------------------------------------------------------------------
// tf32 GEMM: 128 rows/CTA, 8 warps = 4m x 2n (NWT n8-tiles per n-warp,
// NTC = 16*NWT). 3-stage cp.async ring (single sync per chunk).
// NSPLIT: consecutive bx share the same A-slice (L2 reuse of A).
// OMODE 0: fp32 out + ReLU. OMODE 2: fused layer4 + quantum fidelity.
// OCC: __launch_bounds__ min-CTAs-per-SM.
// ---------------------------------------------------------------------------
template<int NWT, int NSPLIT, int OMODE, int OCC>
__global__ __launch_bounds__(256, OCC)
void gemm_tf32(const float* __restrict__ A,
               const unsigned char* __restrict__ Wf,
               const float* __restrict__ bias, void* __restrict__ Out,
               int Ntrue, int K, int nch, int w_rowb,
               const float* __restrict__ W4, const float* __restrict__ b4) {
    extern __shared__ __align__(16) char sm[];
    constexpr int NTC   = NWT * 16;
    constexpr int ABY   = 128 * 128;
    constexpr int STAGE = ABY + NTC * 128;
    constexpr int CSS   = 68;

    const uint32_t sb = smem_u32(sm);
    const int tid  = threadIdx.x;
    const int wid  = tid >> 5;
    const int lane = tid & 31;
    const int g    = lane >> 2;
    const int t    = lane & 3;
    const int mw   = wid & 3;
    const int nw   = wid >> 2;
    const int bx   = blockIdx.x;
    const size_t m0 = (size_t)(bx / NSPLIT) * 128;
    const int n0   = (bx % NSPLIT) * NTC;

    float acc[2][NWT][4];
    #pragma unroll
    for (int mt = 0; mt < 2; mt++)
        #pragma unroll
        for (int j = 0; j < NWT; j++)
            #pragma unroll
            for (int p = 0; p < 4; p++) acc[mt][j][p] = 0.f;

    auto stage = [&](int c, int slot) {
        const uint32_t bufb = sb + slot * STAGE;
        #pragma unroll
        for (int i = 0; i < 4; i++) {
            int f = tid + i * 256;
            int row = f >> 3, j = f & 7;
            int k0 = c * 32 + j * 4;
            int sz = (k0 + 4 <= K) ? 16 : 0;
            const float* src = A + (m0 + row) * (size_t)K + (sz ? k0 : 0);
            cpa16z(bufb + row * 128 + 16 * (j ^ (row & 7)), src, sz);
        }
        #pragma unroll
        for (int i = 0; i < (NTC * 8 + 255) / 256; i++) {
            int f = tid + i * 256;
            if (f < NTC * 8) {
                int row = f >> 3, e = f & 7;
                cpa16(bufb + ABY + row * 128 + 16 * (e ^ ((row & 1) * 4)),
                      Wf + (size_t)(n0 + row) * w_rowb + c * 128 + e * 16);
            }
        }
    };
    auto compute = [&](int slot) {
        const float* Asf = (const float*)(sm + slot * STAGE);
        const char*  Ws  = sm + slot * STAGE + ABY;
        #pragma unroll
        for (int s = 0; s < 2; s++) {
            uint32_t ua[4][4];
            #pragma unroll
            for (int ri = 0; ri < 4; ri++) {
                const float* rb = Asf + (mw * 32 + 8 * ri + g) * 32 + t;
                #pragma unroll
                for (int q = 0; q < 4; q++)
                    ua[ri][q] = to_tf32(rb[4 * ((4 * s + q) ^ g)]);
            }
            #pragma unroll
            for (int j = 0; j < NWT; j++) {
                int wr = (nw * NWT + j) * 8 + g;
                uint4 bb = *(const uint4*)(Ws + wr * 128 +
                                           16 * ((s * 4 + t) ^ ((wr & 1) * 4)));
                mma_tf32(acc[0][j], ua[0][0], ua[1][0], ua[0][1], ua[1][1], bb.x, bb.y);
                mma_tf32(acc[1][j], ua[2][0], ua[3][0], ua[2][1], ua[3][1], bb.x, bb.y);
                mma_tf32(acc[0][j], ua[0][2], ua[1][2], ua[0][3], ua[1][3], bb.z, bb.w);
                mma_tf32(acc[1][j], ua[2][2], ua[3][2], ua[2][3], ua[3][3], bb.z, bb.w);
            }
        }
    };

    stage(0, 0); CP_COMMIT();
    stage(1, 1); CP_COMMIT();
    for (int c = 0; c < nch; ++c) {
        if (c + 1 < nch) { CP_WAIT1(); } else { CP_WAIT0(); }
        __syncthreads();
        compute(c - (c / 3) * 3);
        if (c + 2 < nch) { stage(c + 2, (c + 2) % 3); CP_COMMIT(); }
    }
    __syncthreads();

    if constexpr (OMODE == 0) {
        float* C = (float*)Out;
        #pragma unroll
        for (int mt = 0; mt < 2; mt++) {
            const size_t r = m0 + mw * 32 + mt * 16 + g;
            #pragma unroll
            for (int j = 0; j < NWT; j++) {
                int n = n0 + (nw * NWT + j) * 8 + 2 * t;
                if (n < Ntrue) {
                    float2 b2 = *(const float2*)(bias + n);
                    float v0 = fmaxf(acc[mt][j][0] + b2.x, 0.f);
                    float v1 = fmaxf(acc[mt][j][1] + b2.y, 0.f);
                    float v2 = fmaxf(acc[mt][j][2] + b2.x, 0.f);
                    float v3 = fmaxf(acc[mt][j][3] + b2.y, 0.f);
                    *(float2*)(C + r * Ntrue + n)       = make_float2(v0, v1);
                    *(float2*)(C + (r + 8) * Ntrue + n) = make_float2(v2, v3);
                }
            }
        }
    } else {
        // fused layer4 (50->10, no relu) + quantum fidelity
        float* Cs = (float*)sm;
        #pragma unroll
        for (int mt = 0; mt < 2; mt++) {
            int r = mw * 32 + mt * 16 + g;
            #pragma unroll
            for (int j = 0; j < NWT; j++) {
                int nl = (nw * NWT + j) * 8 + 2 * t;
                float bx2 = (nl     < Ntrue) ? bias[nl]     : 0.f;
                float by2 = (nl + 1 < Ntrue) ? bias[nl + 1] : 0.f;
                float v0 = fmaxf(acc[mt][j][0] + bx2, 0.f);
                float v1 = fmaxf(acc[mt][j][1] + by2, 0.f);
                float v2 = fmaxf(acc[mt][j][2] + bx2, 0.f);
                float v3 = fmaxf(acc[mt][j][3] + by2, 0.f);
                *(float2*)(Cs + r * CSS + nl)       = make_float2(v0, v1);
                *(float2*)(Cs + (r + 8) * CSS + nl) = make_float2(v2, v3);
            }
        }
        float* w4s = (float*)(sm + 128 * CSS * 4);         // 500
        float* b4s = w4s + 500;                            // 10
        float* Ls  = (float*)(sm + 128 * CSS * 4 + 2048);  // [128][11]
        for (int i = tid; i < 500; i += 256) w4s[i] = W4[i];
        if (tid < 10) b4s[tid] = b4[tid];
        __syncthreads();

        if (tid < 128) {
            float l[10];
            #pragma unroll
            for (int j = 0; j < 10; j++) l[j] = b4s[j];
            #pragma unroll 5
            for (int k = 0; k < 50; k++) {
                float hv = Cs[tid * CSS + k];
                #pragma unroll
                for (int j = 0; j < 10; j++) l[j] = fmaf(w4s[j * 50 + k], hv, l[j]);
            }
            #pragma unroll
            for (int j = 0; j < 10; j++) Ls[tid * 11 + j] = l[j];
        }
        __syncthreads();
        if (tid < 64) {
            ((float*)Out)[(size_t)blockIdx.x * 64 + tid] =
                fidelity_from(Ls + 2 * tid * 11, Ls + (2 * tid + 1) * 11);
        }
    }
}

// ---------------------------------------------------------------------------
extern "C" void kernel_launch(void* const* d_in, const int* in_sizes, int n_in,
                              void* d_out, int out_size) {
    const float* x  = (const float*)d_in[0];
    const float* W1 = (const float*)d_in[1];
    const float* b1 = (const float*)d_in[2];
    const float* W2 = (const float*)d_in[3];
    const float* b2 = (const float*)d_in[4];
    const float* W3 = (const float*)d_in[5];
    const float* b3 = (const float*)d_in[6];
    const float* W4 = (const float*)d_in[7];
    const float* b4 = (const float*)d_in[8];

    float *h1, *h2;
    unsigned char *w1f, *w2f, *w3f;
    cudaGetSymbolAddress((void**)&h1,  g_h1);
    cudaGetSymbolAddress((void**)&h2,  g_h2);
    cudaGetSymbolAddress((void**)&w1f, g_w1f);
    cudaGetSymbolAddress((void**)&w2f, g_w2f);
    cudaGetSymbolAddress((void**)&w3f, g_w3f);

    // Weight preps (zero-fill padded rows)
    prep_frag<<<(256 * 20 + 255) / 256, 256>>>(W1, w1f, 256, 200, 300, 20);
    prep_frag<<<(128 * 14 + 255) / 256, 256>>>(W2, w2f, 128, 100, 200, 14);
    prep_frag<<<(64  *  8 + 255) / 256, 256>>>(W3, w3f, 64,  50,  100, 8);

    constexpr int SMEM = 3 * (128 * 128 + 64 * 128);   // 73728
    cudaFuncSetAttribute(gemm_tf32<4, 4, 0, 3>,
                         cudaFuncAttributeMaxDynamicSharedMemorySize, SMEM);
    cudaFuncSetAttribute(gemm_tf32<4, 2, 0, 3>,
                         cudaFuncAttributeMaxDynamicSharedMemorySize, SMEM);
    cudaFuncSetAttribute(gemm_tf32<4, 1, 2, 2>,
                         cudaFuncAttributeMaxDynamicSharedMemorySize, SMEM);

    const int MT = MROWS / 128;   // 1024
    // L1: NTC=64, NSPLIT=4 (256 cols >= 200); consecutive bx share A slice
    gemm_tf32<4, 4, 0, 3><<<MT * 4, 256, SMEM>>>(x,  w1f, b1, h1,
                                                 200, 300, 10, 1280, W4, b4);
    // L2: NTC=64, NSPLIT=2 (128 >= 100)
    gemm_tf32<4, 2, 0, 3><<<MT * 2, 256, SMEM>>>(h1, w2f, b2, h2,
                                                 100, 200, 7, 896, W4, b4);
    // L3: NTC=64 >= 50, fused layer4 + fidelity
    gemm_tf32<4, 1, 2, 2><<<MT,     256, SMEM>>>(h2, w3f, b3, d_out,
                                                 50, 100, 4, 512, W4, b4);
}

// round 12
// speedup vs baseline: 1.2850x; 1.2850x over previous
#include <cuda_runtime.h>
#include <math.h>
#include <cstdint>

// ---------------------------------------------------------------------------
// PreQ round 12: round-8 structure (best measured) + raw-bits tf32 A operands.
//  - A operands plain fp32 (x, h1, h2); cp.async staging with zfill tails
//  - A fragments loaded as RAW fp32 bits (HW truncates to tf32; no cvt.rna
//    in the inner loop -> 32 fewer issue slots per warp-chunk)
//  - W pre-rounded fragment images (RN, unchanged)
//  - 3-stage cp.async ring; L1 y-interleaved N-split; L3 fused tail
// ---------------------------------------------------------------------------

#define MROWS 131072   // 2 * 65536

__device__ float g_h1[(size_t)MROWS * 200];
__device__ float g_h2[(size_t)MROWS * 100];
__device__ __align__(16) unsigned char g_w1f[224 * 1280];
__device__ __align__(16) unsigned char g_w2f[112 * 896];
__device__ __align__(16) unsigned char g_w3f[64 * 512];

// ---------------- helpers ----------------
__device__ __forceinline__ uint32_t smem_u32(const void* p) {
    uint32_t a;
    asm("{ .reg .u64 t; cvta.to.shared.u64 t, %1; cvt.u32.u64 %0, t; }"
        : "=r"(a) : "l"(p));
    return a;
}
__device__ __forceinline__ void cpa16(uint32_t dst, const void* src) {
    asm volatile("cp.async.cg.shared.global [%0], [%1], 16;"
                 :: "r"(dst), "l"(src) : "memory");
}
__device__ __forceinline__ void cpa16z(uint32_t dst, const void* src, int sz) {
    asm volatile("cp.async.cg.shared.global [%0], [%1], 16, %2;"
                 :: "r"(dst), "l"(src), "r"(sz) : "memory");
}
#define CP_COMMIT() asm volatile("cp.async.commit_group;" ::: "memory")
#define CP_WAIT0()  asm volatile("cp.async.wait_group 0;" ::: "memory")
#define CP_WAIT1()  asm volatile("cp.async.wait_group 1;" ::: "memory")

__device__ __forceinline__ uint32_t to_tf32(float f) {
    uint32_t r;
    asm("cvt.rna.tf32.f32 %0, %1;" : "=r"(r) : "f"(f));
    return r;
}
__device__ __forceinline__ void mma_tf32(float c[4],
                                         uint32_t a0, uint32_t a1,
                                         uint32_t a2, uint32_t a3,
                                         uint32_t b0, uint32_t b1) {
    asm volatile(
        "mma.sync.aligned.m16n8k8.row.col.f32.tf32.tf32.f32 "
        "{%0,%1,%2,%3}, {%4,%5,%6,%7}, {%8,%9}, {%0,%1,%2,%3};"
        : "+f"(c[0]), "+f"(c[1]), "+f"(c[2]), "+f"(c[3])
        : "r"(a0), "r"(a1), "r"(a2), "r"(a3), "r"(b0), "r"(b1));
}

// ---------------------------------------------------------------------------
// prep: W[src_rows, K] fp32 -> frag image [nrows_pad][nblk*64B], RN tf32.
// ---------------------------------------------------------------------------
__global__ void prep_frag(const float* __restrict__ S,
                          unsigned char* __restrict__ D,
                          int nrows_pad, int src_rows, int K, int nblk) {
    int f = blockIdx.x * blockDim.x + threadIdx.x;
    if (f >= nrows_pad * nblk) return;
    int row = f / nblk, eb = f - row * nblk;
    int k0 = eb * 16;
    float v[16];
    #pragma unroll
    for (int i = 0; i < 16; i++) v[i] = 0.f;
    if (row < src_rows) {
        #pragma unroll
        for (int i = 0; i < 4; i++) {
            int k = k0 + i * 4;
            if (k < K) {
                float4 q = *(const float4*)(S + (size_t)row * K + k);
                v[i * 4 + 0] = q.x; v[i * 4 + 1] = q.y;
                v[i * 4 + 2] = q.z; v[i * 4 + 3] = q.w;
            }
        }
    }
    uint32_t u[16];
    #pragma unroll
    for (int i = 0; i < 16; i++) u[i] = to_tf32(v[i]);
    unsigned char* dst = D + (size_t)row * (nblk * 64) + (size_t)eb * 64;
    #pragma unroll
    for (int tp = 0; tp < 4; tp++)
        *(uint4*)(dst + tp * 16) =
            make_uint4(u[tp], u[tp + 4], u[tp + 8], u[tp + 12]);
}

// ---------------- quantum math (verified rounds 1-11) ----------------
__device__ __forceinline__ float2 cadd(float2 a, float2 b) {
    return make_float2(a.x + b.x, a.y + b.y);
}
__device__ __forceinline__ float2 csc(float s, float2 a) {
    return make_float2(s * a.x, s * a.y);
}
__device__ __forceinline__ float2 cni(float s, float2 a) {
    return make_float2(s * a.y, -s * a.x);
}
__device__ void applyU(const float* __restrict__ p, float2 x[4]) {
    float c4, s4;
    __sincosf(0.5f * p[4], &s4, &c4);
    float2 y1 = make_float2(c4 * x[1].x + s4 * x[3].y,
                            c4 * x[1].y - s4 * x[3].x);
    float2 y3 = make_float2(s4 * x[1].y + c4 * x[3].x,
                           -s4 * x[1].x + c4 * x[3].y);
    x[1] = y1; x[3] = y3;
    float c2, s2, c3, s3;
    __sincosf(0.5f * p[2], &s2, &c2);
    __sincosf(0.5f * p[3], &s3, &c3);
    float2 t00 = cadd(csc(c3, x[0]), csc(-s3, x[1]));
    float2 t01 = cadd(csc(s3, x[0]), csc( c3, x[1]));
    float2 t10 = cadd(csc(c3, x[2]), csc(-s3, x[3]));
    float2 t11 = cadd(csc(s3, x[2]), csc( c3, x[3]));
    x[0] = cadd(csc(c2, t00), csc(-s2, t10));
    x[1] = cadd(csc(c2, t01), csc(-s2, t11));
    x[2] = cadd(csc(s2, t00), csc( c2, t10));
    x[3] = cadd(csc(s2, t01), csc( c2, t11));
    float c1, s1;
    __sincosf(0.5f * p[1], &s1, &c1);
    float2 u00 = cadd(csc(c1, x[0]), cni(s1, x[1]));
    float2 u01 = cadd(cni(s1, x[0]), csc(c1, x[1]));
    float2 u10 = cadd(csc(c1, x[2]), cni(s1, x[3]));
    float2 u11 = cadd(cni(s1, x[2]), csc(c1, x[3]));
    x[0] = cadd(csc(c1, u00), cni(s1, u10));
    x[1] = cadd(csc(c1, u01), cni(s1, u11));
    x[2] = cadd(cni(s1, u00), csc(c1, u10));
    x[3] = cadd(cni(s1, u01), csc(c1, u11));
}
__device__ __forceinline__ float fidelity_from(const float* l1, const float* l2) {
    float2 s1[4] = {make_float2(1.f, 0.f), make_float2(0.f, 0.f),
                    make_float2(0.f, 0.f), make_float2(0.f, 0.f)};
    applyU(l1, s1);
    applyU(l1 + 5, s1);
    float2 s2[4] = {make_float2(1.f, 0.f), make_float2(0.f, 0.f),
                    make_float2(0.f, 0.f), make_float2(0.f, 0.f)};
    applyU(l2, s2);
    applyU(l2 + 5, s2);
    float re = 0.f, im = 0.f;
    #pragma unroll
    for (int i = 0; i < 4; i++) {
        re += s2[i].x * s1[i].x + s2[i].y * s1[i].y;
        im += s2[i].x * s1[i].y - s2[i].y * s1[i].x;
    }
    return re * re + im * im;
}

// ---------------------------------------------------------------------------
// tf32 GEMM (round-8 structure): 128 rows/CTA, 8 warps = 4m x 2n (NWT n8
// tiles each). K in 32-k chunks, 3-stage cp.async ring.
// A fragments: RAW fp32 bits from smem (HW tf32 truncation; no cvt).
// OMODE 0: fp32 out + ReLU. OMODE 2: fused layer4 + quantum fidelity.
// ---------------------------------------------------------------------------
template<int NWT, int OMODE, bool YSPLIT>
__global__ __launch_bounds__(256, 2)
void gemm_tf32(const float* __restrict__ A,
               const unsigned char* __restrict__ Wf,
               const float* __restrict__ bias, void* __restrict__ Out,
               int Ntrue, int K, int nch, int w_rowb,
               const float* __restrict__ W4, const float* __restrict__ b4) {
    extern __shared__ __align__(16) char sm[];
    constexpr int NTC   = NWT * 16;
    constexpr int ABY   = 128 * 128;
    constexpr int STAGE = ABY + NTC * 128;
    constexpr int CSS   = 68;

    const uint32_t sb = smem_u32(sm);
    const int tid  = threadIdx.x;
    const int wid  = tid >> 5;
    const int lane = tid & 31;
    const int g    = lane >> 2;
    const int t    = lane & 3;
    const int mw   = wid & 3;
    const int nw   = wid >> 2;
    const int bx   = blockIdx.x;
    const size_t m0 = (size_t)(YSPLIT ? (bx >> 1) : bx) * 128;
    const int n0   = YSPLIT ? (bx & 1) * NTC : 0;

    float acc[2][NWT][4];
    #pragma unroll
    for (int mt = 0; mt < 2; mt++)
        #pragma unroll
        for (int j = 0; j < NWT; j++)
            #pragma unroll
            for (int p = 0; p < 4; p++) acc[mt][j][p] = 0.f;

    auto stage = [&](int c, int slot) {
        const uint32_t bufb = sb + slot * STAGE;
        #pragma unroll
        for (int i = 0; i < 4; i++) {
            int f = tid + i * 256;
            int row = f >> 3, j = f & 7;
            int k0 = c * 32 + j * 4;
            int sz = (k0 + 4 <= K) ? 16 : 0;
            const float* src = A + (m0 + row) * (size_t)K + (sz ? k0 : 0);
            cpa16z(bufb + row * 128 + 16 * (j ^ (row & 7)), src, sz);
        }
        #pragma unroll
        for (int i = 0; i < (NTC * 8 + 255) / 256; i++) {
            int f = tid + i * 256;
            if (f < NTC * 8) {
                int row = f >> 3, e = f & 7;
                cpa16(bufb + ABY + row * 128 + 16 * (e ^ ((row & 1) * 4)),
                      Wf + (size_t)(n0 + row) * w_rowb + c * 128 + e * 16);
            }
        }
    };
    auto compute = [&](int slot) {
        const uint32_t* Asu = (const uint32_t*)(sm + slot * STAGE);
        const char*     Ws  = sm + slot * STAGE + ABY;
        #pragma unroll
        for (int s = 0; s < 2; s++) {
            uint32_t ua[4][4];
            #pragma unroll
            for (int ri = 0; ri < 4; ri++) {
                const uint32_t* rb = Asu + (mw * 32 + 8 * ri + g) * 32 + t;
                #pragma unroll
                for (int q = 0; q < 4; q++)
                    ua[ri][q] = rb[4 * ((4 * s + q) ^ g)];   // raw bits, no cvt
            }
            #pragma unroll
            for (int j = 0; j < NWT; j++) {
                int wr = (nw * NWT + j) * 8 + g;
                uint4 bb = *(const uint4*)(Ws + wr * 128 +
                                           16 * ((s * 4 + t) ^ ((wr & 1) * 4)));
                mma_tf32(acc[0][j], ua[0][0], ua[1][0], ua[0][1], ua[1][1], bb.x, bb.y);
                mma_tf32(acc[1][j], ua[2][0], ua[3][0], ua[2][1], ua[3][1], bb.x, bb.y);
                mma_tf32(acc[0][j], ua[0][2], ua[1][2], ua[0][3], ua[1][3], bb.z, bb.w);
                mma_tf32(acc[1][j], ua[2][2], ua[3][2], ua[2][3], ua[3][3], bb.z, bb.w);
            }
        }
    };

    stage(0, 0); CP_COMMIT();
    stage(1, 1); CP_COMMIT();
    for (int c = 0; c < nch; ++c) {
        if (c + 1 < nch) { CP_WAIT1(); } else { CP_WAIT0(); }
        __syncthreads();
        compute(c - (c / 3) * 3);
        if (c + 2 < nch) { stage(c + 2, (c + 2) % 3); CP_COMMIT(); }
    }
    __syncthreads();

    if constexpr (OMODE == 0) {
        float* C = (float*)Out;
        #pragma unroll
        for (int mt = 0; mt < 2; mt++) {
            const size_t r = m0 + mw * 32 + mt * 16 + g;
            #pragma unroll
            for (int j = 0; j < NWT; j++) {
                int n = n0 + (nw * NWT + j) * 8 + 2 * t;
                if (n < Ntrue) {
                    float2 b2 = *(const float2*)(bias + n);
                    float v0 = fmaxf(acc[mt][j][0] + b2.x, 0.f);
                    float v1 = fmaxf(acc[mt][j][1] + b2.y, 0.f);
                    float v2 = fmaxf(acc[mt][j][2] + b2.x, 0.f);
                    float v3 = fmaxf(acc[mt][j][3] + b2.y, 0.f);
                    *(float2*)(C + r * Ntrue + n)       = make_float2(v0, v1);
                    *(float2*)(C + (r + 8) * Ntrue + n) = make_float2(v2, v3);
                }
            }
        }
    } else {
        // fused layer4 (50->10, no relu) + quantum fidelity
        float* Cs = (float*)sm;
        #pragma unroll
        for (int mt = 0; mt < 2; mt++) {
            int r = mw * 32 + mt * 16 + g;
            #pragma unroll
            for (int j = 0; j < NWT; j++) {
                int nl = (nw * NWT + j) * 8 + 2 * t;
                float bx2 = (nl     < Ntrue) ? bias[nl]     : 0.f;
                float by2 = (nl + 1 < Ntrue) ? bias[nl + 1] : 0.f;
                float v0 = fmaxf(acc[mt][j][0] + bx2, 0.f);
                float v1 = fmaxf(acc[mt][j][1] + by2, 0.f);
                float v2 = fmaxf(acc[mt][j][2] + bx2, 0.f);
                float v3 = fmaxf(acc[mt][j][3] + by2, 0.f);
                *(float2*)(Cs + r * CSS + nl)       = make_float2(v0, v1);
                *(float2*)(Cs + (r + 8) * CSS + nl) = make_float2(v2, v3);
            }
        }
        float* w4s = (float*)(sm + 128 * CSS * 4);         // 500
        float* b4s = w4s + 500;                            // 10
        float* Ls  = (float*)(sm + 128 * CSS * 4 + 2048);  // [128][11]
        for (int i = tid; i < 500; i += 256) w4s[i] = W4[i];
        if (tid < 10) b4s[tid] = b4[tid];
        __syncthreads();

        if (tid < 128) {
            float l[10];
            #pragma unroll
            for (int j = 0; j < 10; j++) l[j] = b4s[j];
            #pragma unroll 5
            for (int k = 0; k < 50; k++) {
                float hv = Cs[tid * CSS + k];
                #pragma unroll
                for (int j = 0; j < 10; j++) l[j] = fmaf(w4s[j * 50 + k], hv, l[j]);
            }
            #pragma unroll
            for (int j = 0; j < 10; j++) Ls[tid * 11 + j] = l[j];
        }
        __syncthreads();
        if (tid < 64) {
            ((float*)Out)[(size_t)blockIdx.x * 64 + tid] =
                fidelity_from(Ls + 2 * tid * 11, Ls + (2 * tid + 1) * 11);
        }
    }
}

// ---------------------------------------------------------------------------
extern "C" void kernel_launch(void* const* d_in, const int* in_sizes, int n_in,
                              void* d_out, int out_size) {
    const float* x  = (const float*)d_in[0];
    const float* W1 = (const float*)d_in[1];
    const float* b1 = (const float*)d_in[2];
    const float* W2 = (const float*)d_in[3];
    const float* b2 = (const float*)d_in[4];
    const float* W3 = (const float*)d_in[5];
    const float* b3 = (const float*)d_in[6];
    const float* W4 = (const float*)d_in[7];
    const float* b4 = (const float*)d_in[8];

    float *h1, *h2;
    unsigned char *w1f, *w2f, *w3f;
    cudaGetSymbolAddress((void**)&h1,  g_h1);
    cudaGetSymbolAddress((void**)&h2,  g_h2);
    cudaGetSymbolAddress((void**)&w1f, g_w1f);
    cudaGetSymbolAddress((void**)&w2f, g_w2f);
    cudaGetSymbolAddress((void**)&w3f, g_w3f);

    prep_frag<<<(224 * 20 + 255) / 256, 256>>>(W1, w1f, 224, 200, 300, 20);
    prep_frag<<<(112 * 14 + 255) / 256, 256>>>(W2, w2f, 112, 100, 200, 14);
    prep_frag<<<(64  *  8 + 255) / 256, 256>>>(W3, w3f, 64,  50,  100, 8);

    constexpr int SM12 = 3 * (128 * 128 + 112 * 128);  // 92160
    constexpr int SM3  = 3 * (128 * 128 + 64  * 128);  // 73728
    cudaFuncSetAttribute(gemm_tf32<7, 0, true>,
                         cudaFuncAttributeMaxDynamicSharedMemorySize, SM12);
    cudaFuncSetAttribute(gemm_tf32<7, 0, false>,
                         cudaFuncAttributeMaxDynamicSharedMemorySize, SM12);
    cudaFuncSetAttribute(gemm_tf32<4, 2, false>,
                         cudaFuncAttributeMaxDynamicSharedMemorySize, SM3);

    const int MT = MROWS / 128;   // 1024
    // L1: A = x [2B,300] fp32, y-interleaved split (NTC=112 covers 224>=200)
    gemm_tf32<7, 0, true ><<<MT * 2, 256, SM12>>>(x,  w1f, b1, h1,
                                                  200, 300, 10, 1280, W4, b4);
    // L2: A = h1 [M,200] fp32, NTC=112 covers 100
    gemm_tf32<7, 0, false><<<MT,     256, SM12>>>(h1, w2f, b2, h2,
                                                  100, 200, 7, 896, W4, b4);
    // L3: A = h2 [M,100] fp32, NTC=64 covers 50, fused layer4 + fidelity
    gemm_tf32<4, 2, false><<<MT,     256, SM3 >>>(h2, w3f, b3, d_out,
                                                  50, 100, 4, 512, W4, b4);
}

// round 13
// speedup vs baseline: 1.2892x; 1.0032x over previous
#include <cuda_runtime.h>
#include <math.h>
#include <cstdint>

// ---------------------------------------------------------------------------
// PreQ round 13: round-12 (best: 207.6us) + swizzle-free A smem layout.
//  - A smem rows padded to 36 floats (144B): bank = (4g+t+c) mod 32, all
//    distinct -> conflict-free LDS.32 with IMMEDIATE offsets (no XOR ALU).
//  - A fragments raw fp32 bits (HW tf32 truncation), W RN frag images.
//  - 3-stage cp.async ring; L1 y-interleaved N-split; L3 fused tail.
// ---------------------------------------------------------------------------

#define MROWS 131072   // 2 * 65536
#define ASTR  36       // A smem row stride in floats (144B)

__device__ float g_h1[(size_t)MROWS * 200];
__device__ float g_h2[(size_t)MROWS * 100];
__device__ __align__(16) unsigned char g_w1f[224 * 1280];
__device__ __align__(16) unsigned char g_w2f[112 * 896];
__device__ __align__(16) unsigned char g_w3f[64 * 512];

// ---------------- helpers ----------------
__device__ __forceinline__ uint32_t smem_u32(const void* p) {
    uint32_t a;
    asm("{ .reg .u64 t; cvta.to.shared.u64 t, %1; cvt.u32.u64 %0, t; }"
        : "=r"(a) : "l"(p));
    return a;
}
__device__ __forceinline__ void cpa16(uint32_t dst, const void* src) {
    asm volatile("cp.async.cg.shared.global [%0], [%1], 16;"
                 :: "r"(dst), "l"(src) : "memory");
}
__device__ __forceinline__ void cpa16z(uint32_t dst, const void* src, int sz) {
    asm volatile("cp.async.cg.shared.global [%0], [%1], 16, %2;"
                 :: "r"(dst), "l"(src), "r"(sz) : "memory");
}
#define CP_COMMIT() asm volatile("cp.async.commit_group;" ::: "memory")
#define CP_WAIT0()  asm volatile("cp.async.wait_group 0;" ::: "memory")
#define CP_WAIT1()  asm volatile("cp.async.wait_group 1;" ::: "memory")

__device__ __forceinline__ uint32_t to_tf32(float f) {
    uint32_t r;
    asm("cvt.rna.tf32.f32 %0, %1;" : "=r"(r) : "f"(f));
    return r;
}
__device__ __forceinline__ void mma_tf32(float c[4],
                                         uint32_t a0, uint32_t a1,
                                         uint32_t a2, uint32_t a3,
                                         uint32_t b0, uint32_t b1) {
    asm volatile(
        "mma.sync.aligned.m16n8k8.row.col.f32.tf32.tf32.f32 "
        "{%0,%1,%2,%3}, {%4,%5,%6,%7}, {%8,%9}, {%0,%1,%2,%3};"
        : "+f"(c[0]), "+f"(c[1]), "+f"(c[2]), "+f"(c[3])
        : "r"(a0), "r"(a1), "r"(a2), "r"(a3), "r"(b0), "r"(b1));
}

// ---------------------------------------------------------------------------
// prep: W[src_rows, K] fp32 -> frag image [nrows_pad][nblk*64B], RN tf32.
// ---------------------------------------------------------------------------
__global__ void prep_frag(const float* __restrict__ S,
                          unsigned char* __restrict__ D,
                          int nrows_pad, int src_rows, int K, int nblk) {
    int f = blockIdx.x * blockDim.x + threadIdx.x;
    if (f >= nrows_pad * nblk) return;
    int row = f / nblk, eb = f - row * nblk;
    int k0 = eb * 16;
    float v[16];
    #pragma unroll
    for (int i = 0; i < 16; i++) v[i] = 0.f;
    if (row < src_rows) {
        #pragma unroll
        for (int i = 0; i < 4; i++) {
            int k = k0 + i * 4;
            if (k < K) {
                float4 q = *(const float4*)(S + (size_t)row * K + k);
                v[i * 4 + 0] = q.x; v[i * 4 + 1] = q.y;
                v[i * 4 + 2] = q.z; v[i * 4 + 3] = q.w;
            }
        }
    }
    uint32_t u[16];
    #pragma unroll
    for (int i = 0; i < 16; i++) u[i] = to_tf32(v[i]);
    unsigned char* dst = D + (size_t)row * (nblk * 64) + (size_t)eb * 64;
    #pragma unroll
    for (int tp = 0; tp < 4; tp++)
        *(uint4*)(dst + tp * 16) =
            make_uint4(u[tp], u[tp + 4], u[tp + 8], u[tp + 12]);
}

// ---------------- quantum math (verified rounds 1-12) ----------------
__device__ __forceinline__ float2 cadd(float2 a, float2 b) {
    return make_float2(a.x + b.x, a.y + b.y);
}
__device__ __forceinline__ float2 csc(float s, float2 a) {
    return make_float2(s * a.x, s * a.y);
}
__device__ __forceinline__ float2 cni(float s, float2 a) {
    return make_float2(s * a.y, -s * a.x);
}
__device__ void applyU(const float* __restrict__ p, float2 x[4]) {
    float c4, s4;
    __sincosf(0.5f * p[4], &s4, &c4);
    float2 y1 = make_float2(c4 * x[1].x + s4 * x[3].y,
                            c4 * x[1].y - s4 * x[3].x);
    float2 y3 = make_float2(s4 * x[1].y + c4 * x[3].x,
                           -s4 * x[1].x + c4 * x[3].y);
    x[1] = y1; x[3] = y3;
    float c2, s2, c3, s3;
    __sincosf(0.5f * p[2], &s2, &c2);
    __sincosf(0.5f * p[3], &s3, &c3);
    float2 t00 = cadd(csc(c3, x[0]), csc(-s3, x[1]));
    float2 t01 = cadd(csc(s3, x[0]), csc( c3, x[1]));
    float2 t10 = cadd(csc(c3, x[2]), csc(-s3, x[3]));
    float2 t11 = cadd(csc(s3, x[2]), csc( c3, x[3]));
    x[0] = cadd(csc(c2, t00), csc(-s2, t10));
    x[1] = cadd(csc(c2, t01), csc(-s2, t11));
    x[2] = cadd(csc(s2, t00), csc( c2, t10));
    x[3] = cadd(csc(s2, t01), csc( c2, t11));
    float c1, s1;
    __sincosf(0.5f * p[1], &s1, &c1);
    float2 u00 = cadd(csc(c1, x[0]), cni(s1, x[1]));
    float2 u01 = cadd(cni(s1, x[0]), csc(c1, x[1]));
    float2 u10 = cadd(csc(c1, x[2]), cni(s1, x[3]));
    float2 u11 = cadd(cni(s1, x[2]), csc(c1, x[3]));
    x[0] = cadd(csc(c1, u00), cni(s1, u10));
    x[1] = cadd(csc(c1, u01), cni(s1, u11));
    x[2] = cadd(cni(s1, u00), csc(c1, u10));
    x[3] = cadd(cni(s1, u01), csc(c1, u11));
}
__device__ __forceinline__ float fidelity_from(const float* l1, const float* l2) {
    float2 s1[4] = {make_float2(1.f, 0.f), make_float2(0.f, 0.f),
                    make_float2(0.f, 0.f), make_float2(0.f, 0.f)};
    applyU(l1, s1);
    applyU(l1 + 5, s1);
    float2 s2[4] = {make_float2(1.f, 0.f), make_float2(0.f, 0.f),
                    make_float2(0.f, 0.f), make_float2(0.f, 0.f)};
    applyU(l2, s2);
    applyU(l2 + 5, s2);
    float re = 0.f, im = 0.f;
    #pragma unroll
    for (int i = 0; i < 4; i++) {
        re += s2[i].x * s1[i].x + s2[i].y * s1[i].y;
        im += s2[i].x * s1[i].y - s2[i].y * s1[i].x;
    }
    return re * re + im * im;
}

// ---------------------------------------------------------------------------
// tf32 GEMM: 128 rows/CTA, 8 warps = 4m x 2n (NWT n8 tiles each).
// K in 32-k chunks, 3-stage cp.async ring.
// A smem: 128 rows x 36 floats (144B stride), no swizzle; LDS.32 imm offsets.
// W smem: NTC rows x 128B, row-parity XOR (LDS.128, conflict-free).
// OMODE 0: fp32 out + ReLU. OMODE 2: fused layer4 + quantum fidelity.
// ---------------------------------------------------------------------------
template<int NWT, int OMODE, bool YSPLIT>
__global__ __launch_bounds__(256, 2)
void gemm_tf32(const float* __restrict__ A,
               const unsigned char* __restrict__ Wf,
               const float* __restrict__ bias, void* __restrict__ Out,
               int Ntrue, int K, int nch, int w_rowb,
               const float* __restrict__ W4, const float* __restrict__ b4) {
    extern __shared__ __align__(16) char sm[];
    constexpr int NTC   = NWT * 16;
    constexpr int ABY   = 128 * ASTR * 4;     // 18432
    constexpr int STAGE = ABY + NTC * 128;
    constexpr int CSS   = 68;

    const uint32_t sb = smem_u32(sm);
    const int tid  = threadIdx.x;
    const int wid  = tid >> 5;
    const int lane = tid & 31;
    const int g    = lane >> 2;
    const int t    = lane & 3;
    const int mw   = wid & 3;
    const int nw   = wid >> 2;
    const int bx   = blockIdx.x;
    const size_t m0 = (size_t)(YSPLIT ? (bx >> 1) : bx) * 128;
    const int n0   = YSPLIT ? (bx & 1) * NTC : 0;

    float acc[2][NWT][4];
    #pragma unroll
    for (int mt = 0; mt < 2; mt++)
        #pragma unroll
        for (int j = 0; j < NWT; j++)
            #pragma unroll
            for (int p = 0; p < 4; p++) acc[mt][j][p] = 0.f;

    auto stage = [&](int c, int slot) {
        const uint32_t bufb = sb + slot * STAGE;
        // A: 128 rows x 8 16B-groups, stride 144B, zfill tails
        #pragma unroll
        for (int i = 0; i < 4; i++) {
            int f = tid + i * 256;
            int row = f >> 3, j = f & 7;
            int k0 = c * 32 + j * 4;
            int sz = (k0 + 4 <= K) ? 16 : 0;
            const float* src = A + (m0 + row) * (size_t)K + (sz ? k0 : 0);
            cpa16z(bufb + row * 144 + j * 16, src, sz);
        }
        // W: NTC rows x 8 entries, row-parity swizzle (unchanged)
        #pragma unroll
        for (int i = 0; i < (NTC * 8 + 255) / 256; i++) {
            int f = tid + i * 256;
            if (f < NTC * 8) {
                int row = f >> 3, e = f & 7;
                cpa16(bufb + ABY + row * 128 + 16 * (e ^ ((row & 1) * 4)),
                      Wf + (size_t)(n0 + row) * w_rowb + c * 128 + e * 16);
            }
        }
    };
    auto compute = [&](int slot) {
        const uint32_t* Asu = (const uint32_t*)(sm + slot * STAGE);
        const char*     Ws  = sm + slot * STAGE + ABY;
        // per-thread row bases (computed once; all k offsets are immediates)
        const uint32_t* rb0 = Asu + (mw * 32 +      g) * ASTR + t;
        const uint32_t* rb1 = Asu + (mw * 32 +  8 + g) * ASTR + t;
        const uint32_t* rb2 = Asu + (mw * 32 + 16 + g) * ASTR + t;
        const uint32_t* rb3 = Asu + (mw * 32 + 24 + g) * ASTR + t;
        #pragma unroll
        for (int s = 0; s < 2; s++) {
            uint32_t ua[4][4];
            #pragma unroll
            for (int q = 0; q < 4; q++) {
                ua[0][q] = rb0[16 * s + 4 * q];
                ua[1][q] = rb1[16 * s + 4 * q];
                ua[2][q] = rb2[16 * s + 4 * q];
                ua[3][q] = rb3[16 * s + 4 * q];
            }
            #pragma unroll
            for (int j = 0; j < NWT; j++) {
                int wr = (nw * NWT + j) * 8 + g;
                uint4 bb = *(const uint4*)(Ws + wr * 128 +
                                           16 * ((s * 4 + t) ^ ((wr & 1) * 4)));
                mma_tf32(acc[0][j], ua[0][0], ua[1][0], ua[0][1], ua[1][1], bb.x, bb.y);
                mma_tf32(acc[1][j], ua[2][0], ua[3][0], ua[2][1], ua[3][1], bb.x, bb.y);
                mma_tf32(acc[0][j], ua[0][2], ua[1][2], ua[0][3], ua[1][3], bb.z, bb.w);
                mma_tf32(acc[1][j], ua[2][2], ua[3][2], ua[2][3], ua[3][3], bb.z, bb.w);
            }
        }
    };

    stage(0, 0); CP_COMMIT();
    stage(1, 1); CP_COMMIT();
    for (int c = 0; c < nch; ++c) {
        if (c + 1 < nch) { CP_WAIT1(); } else { CP_WAIT0(); }
        __syncthreads();
        compute(c - (c / 3) * 3);
        if (c + 2 < nch) { stage(c + 2, (c + 2) % 3); CP_COMMIT(); }
    }
    __syncthreads();

    if constexpr (OMODE == 0) {
        float* C = (float*)Out;
        #pragma unroll
        for (int mt = 0; mt < 2; mt++) {
            const size_t r = m0 + mw * 32 + mt * 16 + g;
            #pragma unroll
            for (int j = 0; j < NWT; j++) {
                int n = n0 + (nw * NWT + j) * 8 + 2 * t;
                if (n < Ntrue) {
                    float2 b2 = *(const float2*)(bias + n);
                    float v0 = fmaxf(acc[mt][j][0] + b2.x, 0.f);
                    float v1 = fmaxf(acc[mt][j][1] + b2.y, 0.f);
                    float v2 = fmaxf(acc[mt][j][2] + b2.x, 0.f);
                    float v3 = fmaxf(acc[mt][j][3] + b2.y, 0.f);
                    *(float2*)(C + r * Ntrue + n)       = make_float2(v0, v1);
                    *(float2*)(C + (r + 8) * Ntrue + n) = make_float2(v2, v3);
                }
            }
        }
    } else {
        // fused layer4 (50->10, no relu) + quantum fidelity
        float* Cs = (float*)sm;
        #pragma unroll
        for (int mt = 0; mt < 2; mt++) {
            int r = mw * 32 + mt * 16 + g;
            #pragma unroll
            for (int j = 0; j < NWT; j++) {
                int nl = (nw * NWT + j) * 8 + 2 * t;
                float bx2 = (nl     < Ntrue) ? bias[nl]     : 0.f;
                float by2 = (nl + 1 < Ntrue) ? bias[nl + 1] : 0.f;
                float v0 = fmaxf(acc[mt][j][0] + bx2, 0.f);
                float v1 = fmaxf(acc[mt][j][1] + by2, 0.f);
                float v2 = fmaxf(acc[mt][j][2] + bx2, 0.f);
                float v3 = fmaxf(acc[mt][j][3] + by2, 0.f);
                *(float2*)(Cs + r * CSS + nl)       = make_float2(v0, v1);
                *(float2*)(Cs + (r + 8) * CSS + nl) = make_float2(v2, v3);
            }
        }
        float* w4s = (float*)(sm + 128 * CSS * 4);         // 500
        float* b4s = w4s + 500;                            // 10
        float* Ls  = (float*)(sm + 128 * CSS * 4 + 2048);  // [128][11]
        for (int i = tid; i < 500; i += 256) w4s[i] = W4[i];
        if (tid < 10) b4s[tid] = b4[tid];
        __syncthreads();

        if (tid < 128) {
            float l[10];
            #pragma unroll
            for (int j = 0; j < 10; j++) l[j] = b4s[j];
            #pragma unroll 5
            for (int k = 0; k < 50; k++) {
                float hv = Cs[tid * CSS + k];
                #pragma unroll
                for (int j = 0; j < 10; j++) l[j] = fmaf(w4s[j * 50 + k], hv, l[j]);
            }
            #pragma unroll
            for (int j = 0; j < 10; j++) Ls[tid * 11 + j] = l[j];
        }
        __syncthreads();
        if (tid < 64) {
            ((float*)Out)[(size_t)blockIdx.x * 64 + tid] =
                fidelity_from(Ls + 2 * tid * 11, Ls + (2 * tid + 1) * 11);
        }
    }
}

// ---------------------------------------------------------------------------
extern "C" void kernel_launch(void* const* d_in, const int* in_sizes, int n_in,
                              void* d_out, int out_size) {
    const float* x  = (const float*)d_in[0];
    const float* W1 = (const float*)d_in[1];
    const float* b1 = (const float*)d_in[2];
    const float* W2 = (const float*)d_in[3];
    const float* b2 = (const float*)d_in[4];
    const float* W3 = (const float*)d_in[5];
    const float* b3 = (const float*)d_in[6];
    const float* W4 = (const float*)d_in[7];
    const float* b4 = (const float*)d_in[8];

    float *h1, *h2;
    unsigned char *w1f, *w2f, *w3f;
    cudaGetSymbolAddress((void**)&h1,  g_h1);
    cudaGetSymbolAddress((void**)&h2,  g_h2);
    cudaGetSymbolAddress((void**)&w1f, g_w1f);
    cudaGetSymbolAddress((void**)&w2f, g_w2f);
    cudaGetSymbolAddress((void**)&w3f, g_w3f);

    prep_frag<<<(224 * 20 + 255) / 256, 256>>>(W1, w1f, 224, 200, 300, 20);
    prep_frag<<<(112 * 14 + 255) / 256, 256>>>(W2, w2f, 112, 100, 200, 14);
    prep_frag<<<(64  *  8 + 255) / 256, 256>>>(W3, w3f, 64,  50,  100, 8);

    constexpr int SM12 = 3 * (128 * 144 + 112 * 128);  // 98304
    constexpr int SM3  = 3 * (128 * 144 + 64  * 128);  // 79872
    cudaFuncSetAttribute(gemm_tf32<7, 0, true>,
                         cudaFuncAttributeMaxDynamicSharedMemorySize, SM12);
    cudaFuncSetAttribute(gemm_tf32<7, 0, false>,
                         cudaFuncAttributeMaxDynamicSharedMemorySize, SM12);
    cudaFuncSetAttribute(gemm_tf32<4, 2, false>,
                         cudaFuncAttributeMaxDynamicSharedMemorySize, SM3);

    const int MT = MROWS / 128;   // 1024
    // L1: A = x [2B,300] fp32, y-interleaved split (NTC=112 covers 224>=200)
    gemm_tf32<7, 0, true ><<<MT * 2, 256, SM12>>>(x,  w1f, b1, h1,
                                                  200, 300, 10, 1280, W4, b4);
    // L2: A = h1 [M,200] fp32, NTC=112 covers 100
    gemm_tf32<7, 0, false><<<MT,     256, SM12>>>(h1, w2f, b2, h2,
                                                  100, 200, 7, 896, W4, b4);
    // L3: A = h2 [M,100] fp32, NTC=64 covers 50, fused layer4 + fidelity
    gemm_tf32<4, 2, false><<<MT,     256, SM3 >>>(h2, w3f, b3, d_out,
                                                  50, 100, 4, 512, W4, b4);
}